// round 1
// baseline (speedup 1.0000x reference)
#include <cuda_runtime.h>
#include <cuda_bf16.h>
#include <math.h>

#define BB 4096
#define LL 200
#define FF 8
#define DD 64
#define KK 15

__global__ void __launch_bounds__(256) search_predict_kernel(
    const int* __restrict__ x,        // [B, L, F] int32
    const int* __restrict__ self_loc, // [B] int32
    const float* __restrict__ E,      // [NFEAT+1, D] float32
    float* __restrict__ out)          // [B*16*8] x_out-as-float, then [B*15] sim_topk
{
    const int b    = blockIdx.x;
    const int tid  = threadIdx.x;
    const int warp = tid >> 5;
    const int lane = tid & 31;

    __shared__ float e_self_x[32];   // split even/odd to avoid bank gymnastics
    __shared__ float e_self_y[32];
    __shared__ float sim[LL];
    __shared__ float n_self_s;
    __shared__ int   sl_s;
    __shared__ int   selIdx[KK];
    __shared__ float selVal[KK];

    const int* xb = x + (size_t)b * (LL * FF);

    if (tid == 0) sl_s = self_loc[b];
    __syncthreads();
    const int sl = sl_s;

    // --- warp 0: load self embedding row, compute its norm ---
    if (warp == 0) {
        const int cat_self = xb[sl * FF + 5];
        const float2* row = reinterpret_cast<const float2*>(E + (size_t)cat_self * DD);
        float2 v = row[lane];
        e_self_x[lane] = v.x;
        e_self_y[lane] = v.y;
        float ssq = v.x * v.x + v.y * v.y;
        #pragma unroll
        for (int o = 16; o; o >>= 1) ssq += __shfl_xor_sync(0xffffffffu, ssq, o);
        if (lane == 0) n_self_s = sqrtf(ssq + 1e-8f);
    }
    __syncthreads();

    const float n_self = n_self_s;
    const float sx = e_self_x[lane];
    const float sy = e_self_y[lane];

    // --- each warp computes cosine sims for its rows ---
    const int nwarp = blockDim.x >> 5;
    for (int l = warp; l < LL; l += nwarp) {
        float s;
        if (l < sl) {
            const int c = xb[l * FF + 5];
            const float2* row = reinterpret_cast<const float2*>(E + (size_t)c * DD);
            float2 v = row[lane];
            float dot = v.x * sx + v.y * sy;
            float ssq = v.x * v.x + v.y * v.y;
            #pragma unroll
            for (int o = 16; o; o >>= 1) {
                dot += __shfl_xor_sync(0xffffffffu, dot, o);
                ssq += __shfl_xor_sync(0xffffffffu, ssq, o);
            }
            s = dot / (sqrtf(ssq + 1e-8f) * n_self);
        } else {
            s = -2.0f;
        }
        if (lane == 0) sim[l] = s;
    }
    __syncthreads();

    // --- warp 0: K argmax passes (tie-break: lowest index), matching lax.top_k ---
    if (warp == 0) {
        for (int k = 0; k < KK; k++) {
            float bestV = -3.0f;
            int   bestI = LL;
            for (int l = lane; l < LL; l += 32) {
                float v = sim[l];
                if (v > bestV || (v == bestV && l < bestI)) { bestV = v; bestI = l; }
            }
            #pragma unroll
            for (int o = 16; o; o >>= 1) {
                float ov = __shfl_xor_sync(0xffffffffu, bestV, o);
                int   oi = __shfl_xor_sync(0xffffffffu, bestI, o);
                if (ov > bestV || (ov == bestV && oi < bestI)) { bestV = ov; bestI = oi; }
            }
            if (lane == 0) {
                selIdx[k] = bestI;
                selVal[k] = bestV;
                sim[bestI] = -3.0f;   // exclude from later passes
            }
            __syncwarp();
        }
        // sort selected (idx, val) pairs by ascending index (jnp.sort(idx))
        if (lane == 0) {
            for (int i = 1; i < KK; i++) {
                int ii = selIdx[i]; float vv = selVal[i];
                int j = i - 1;
                while (j >= 0 && selIdx[j] > ii) {
                    selIdx[j + 1] = selIdx[j];
                    selVal[j + 1] = selVal[j];
                    j--;
                }
                selIdx[j + 1] = ii;
                selVal[j + 1] = vv;
            }
        }
    }
    __syncthreads();

    // --- outputs ---
    // x_out: [B, 16, 8] as float (rows 0..14 = top-k rows of x, row 15 = self row)
    if (tid < (KK + 1) * FF) {
        const int r = tid >> 3;
        const int f = tid & 7;
        const int l = (r < KK) ? selIdx[r] : sl;
        out[(size_t)b * ((KK + 1) * FF) + r * FF + f] = (float)xb[l * FF + f];
    }
    // sim_topk: [B, 15] appended after x_out block
    if (tid < KK) {
        out[(size_t)BB * ((KK + 1) * FF) + (size_t)b * KK + tid] = selVal[tid];
    }
}

extern "C" void kernel_launch(void* const* d_in, const int* in_sizes, int n_in,
                              void* d_out, int out_size) {
    const int*   x  = (const int*)d_in[0];   // x: [4096, 200, 8] int32
    const int*   sl = (const int*)d_in[1];   // self_loc: [4096] int32
    const float* E  = (const float*)d_in[2]; // E: [100001, 64] float32
    float* out = (float*)d_out;

    search_predict_kernel<<<BB, 256>>>(x, sl, E, out);
}

// round 3
// speedup vs baseline: 1.3338x; 1.3338x over previous
#include <cuda_runtime.h>
#include <cuda_bf16.h>
#include <math.h>

#define BB 4096
#define LL 200
#define FF 8
#define DD 64
#define KK 15

__device__ __forceinline__ unsigned enc_f(float f) {
    unsigned u = __float_as_uint(f);
    return (u >> 31) ? ~u : (u ^ 0x80000000u);
}
__device__ __forceinline__ float dec_f(unsigned u) {
    unsigned bits = (u & 0x80000000u) ? (u ^ 0x80000000u) : ~u;
    return __uint_as_float(bits);
}

__global__ void __launch_bounds__(256) search_predict_kernel(
    const int* __restrict__ x,        // [B, L, F] int32
    const int* __restrict__ self_loc, // [B] int32
    const float* __restrict__ E,      // [NFEAT+1, D] float32
    float* __restrict__ out)          // [B*16*8] x_out-as-float, then [B*15] sim_topk
{
    const int b    = blockIdx.x;
    const int tid  = threadIdx.x;
    const int warp = tid >> 5;
    const int lane = tid & 31;
    const int grp  = lane >> 3;   // 4 groups of 8 lanes per warp; 1 row per group
    const int gl   = lane & 7;    // lane within group: covers 32B of a 256B row

    __shared__ __align__(16) unsigned long long keys[LL];
    __shared__ unsigned long long selKey[KK];
    __shared__ int sortedL[KK + 1];

    const int* xb = x + (size_t)b * (LL * FF);
    const int sl = __ldg(self_loc + b);          // broadcast load, no sync needed

    // --- self embedding: every 8-lane group loads the full self row (broadcast) ---
    const int cself = __ldg(xb + sl * FF + 5);
    const float4* srow = reinterpret_cast<const float4*>(E + (size_t)cself * DD);
    const float4 s0 = __ldg(srow + gl * 2);
    const float4 s1 = __ldg(srow + gl * 2 + 1);
    float ssq_s = s0.x*s0.x + s0.y*s0.y + s0.z*s0.z + s0.w*s0.w
                + s1.x*s1.x + s1.y*s1.y + s1.z*s1.z + s1.w*s1.w;
    ssq_s += __shfl_xor_sync(0xffffffffu, ssq_s, 4);
    ssq_s += __shfl_xor_sync(0xffffffffu, ssq_s, 2);
    ssq_s += __shfl_xor_sync(0xffffffffu, ssq_s, 1);
    const float inv_nself = rsqrtf(ssq_s + 1e-8f);

    // --- cosine sims: 32 rows/block-iter (4 rows/warp), branch-free, fully unrolled ---
    #pragma unroll
    for (int it = 0; it < 7; ++it) {
        const int l    = it * 32 + warp * 4 + grp;       // unique l in [0, 224)
        const int lidx = (l < LL) ? l : (LL - 1);        // clamp for safe loads
        const int c = __ldg(xb + lidx * FF + 5);         // always in-bounds in E
        const float4* row = reinterpret_cast<const float4*>(E + (size_t)c * DD);
        const float4 v0 = __ldg(row + gl * 2);
        const float4 v1 = __ldg(row + gl * 2 + 1);
        float dot = v0.x*s0.x + v0.y*s0.y + v0.z*s0.z + v0.w*s0.w
                  + v1.x*s1.x + v1.y*s1.y + v1.z*s1.z + v1.w*s1.w;
        float ssq = v0.x*v0.x + v0.y*v0.y + v0.z*v0.z + v0.w*v0.w
                  + v1.x*v1.x + v1.y*v1.y + v1.z*v1.z + v1.w*v1.w;
        // full-mask shuffles, executed by ALL lanes (no divergence)
        dot += __shfl_xor_sync(0xffffffffu, dot, 4);
        ssq += __shfl_xor_sync(0xffffffffu, ssq, 4);
        dot += __shfl_xor_sync(0xffffffffu, dot, 2);
        ssq += __shfl_xor_sync(0xffffffffu, ssq, 2);
        dot += __shfl_xor_sync(0xffffffffu, dot, 1);
        ssq += __shfl_xor_sync(0xffffffffu, ssq, 1);
        const float val = dot * rsqrtf(ssq + 1e-8f) * inv_nself;
        const float sim = (l < sl) ? val : -2.0f;
        if (gl == 0 && l < LL) {
            // monotone key: larger sim wins; tie -> smaller index wins
            keys[l] = ((unsigned long long)enc_f(sim) << 32)
                    | (unsigned)(LL - 1 - l);
        }
    }
    __syncthreads();

    // --- parallel rank-select: rank(t) = #keys greater than key(t); keys unique ---
    {
        const unsigned long long myKey = (tid < LL) ? keys[tid] : 0ull;
        int rank = 0;
        const ulonglong2* k2 = reinterpret_cast<const ulonglong2*>(keys);
        #pragma unroll 10
        for (int j = 0; j < LL / 2; ++j) {          // broadcast LDS.128, conflict-free
            const ulonglong2 kk = k2[j];
            rank += (kk.x > myKey);
            rank += (kk.y > myKey);
        }
        if (tid < LL && rank < KK) selKey[rank] = myKey;
    }
    __syncthreads();

    // --- sort the 15 selected by ascending index; emit sim_topk ---
    if (tid < KK) {
        const unsigned long long mk = selKey[tid];
        const unsigned myLow = (unsigned)mk;        // 199 - l (larger = smaller l)
        int pos = 0;
        #pragma unroll
        for (int j = 0; j < KK; ++j) pos += ((unsigned)selKey[j] > myLow);
        const int l = LL - 1 - (int)myLow;
        sortedL[pos] = l;
        out[(size_t)BB * ((KK + 1) * FF) + (size_t)b * KK + pos] = dec_f((unsigned)(mk >> 32));
    }
    if (tid == KK) sortedL[KK] = sl;
    __syncthreads();

    // --- x_out: [16 rows x 8 feats] as float ---
    if (tid < (KK + 1) * FF) {
        const int r = tid >> 3;
        const int f = tid & 7;
        const int l = sortedL[r];
        out[(size_t)b * ((KK + 1) * FF) + tid] = (float)__ldg(xb + l * FF + f);
    }
}

extern "C" void kernel_launch(void* const* d_in, const int* in_sizes, int n_in,
                              void* d_out, int out_size) {
    const int*   x  = (const int*)d_in[0];   // x: [4096, 200, 8] int32
    const int*   sl = (const int*)d_in[1];   // self_loc: [4096] int32
    const float* E  = (const float*)d_in[2]; // E: [100001, 64] float32
    float* out = (float*)d_out;

    search_predict_kernel<<<BB, 256>>>(x, sl, E, out);
}